// round 14
// baseline (speedup 1.0000x reference)
#include <cuda_runtime.h>
#include <math.h>

#define NFFT   512
#define HOP    480
#define NBINS  257
#define BATCH  8
#define LSIG   88200
#define NT     184
#define NFR    4                      // frames per block (2 groups x 2 packed)
#define NTHREADS 256
#define NBLKS  (BATCH * NT / NFR)     // 368 blocks
#define BARKMID 12.37

__device__ float g_partial[NBLKS];
__device__ unsigned int g_count = 0;

// ===========================================================================
// constexpr fp64 math (compile-time) — series-based, ~1e-14 accurate
// ===========================================================================
constexpr double c_sqrt(double x) {
    double g = x > 1.0 ? x : 1.0;
    for (int i = 0; i < 80; i++) g = 0.5 * (g + x / g);
    return g;
}
constexpr double c_exp(double x) {
    const double ln2 = 0.69314718055994530942;
    int k = (int)(x / ln2 + (x >= 0 ? 0.5 : -0.5));
    double r = x - (double)k * ln2;
    double term = 1.0, sum = 1.0;
    for (int i = 1; i <= 22; i++) { term *= r / (double)i; sum += term; }
    double p = 1.0;
    if (k >= 0) { for (int i = 0; i < k;  i++) p *= 2.0; }
    else        { for (int i = 0; i < -k; i++) p *= 0.5; }
    return sum * p;
}
constexpr double c_log(double x) {
    int k = 0; double m = x;
    while (m >= 2.0) { m *= 0.5; k++; }
    while (m < 1.0)  { m *= 2.0; k--; }
    double t = (m - 1.0) / (m + 1.0), t2 = t * t, term = t, sum = 0.0;
    for (int i = 0; i < 45; i++) { sum += term / (double)(2 * i + 1); term *= t2; }
    return 2.0 * sum + (double)k * 0.69314718055994530942;
}
constexpr double c_pow(double x, double y) { return c_exp(y * c_log(x)); }
constexpr double c_atan(double x) {
    if (x < 0.0) return -c_atan(-x);
    if (x > 1.0) return 1.57079632679489661923 - c_atan(1.0 / x);
    double x1 = x  / (1.0 + c_sqrt(1.0 + x  * x));
    double x2 = x1 / (1.0 + c_sqrt(1.0 + x1 * x1));
    double t2 = x2 * x2, term = x2, sum = 0.0;
    for (int i = 0; i < 26; i++) {
        sum += ((i & 1) ? -term : term) / (double)(2 * i + 1);
        term *= t2;
    }
    return 4.0 * sum;
}
constexpr double c_cospi(double x) {
    double y = x;
    while (y >= 2.0) y -= 2.0;
    while (y < 0.0)  y += 2.0;
    double sign = 1.0;
    if (y > 1.0) y = 2.0 - y;
    if (y > 0.5) { y = 1.0 - y; sign = -1.0; }
    double a = y * 3.14159265358979323846;
    double a2 = a * a, term = 1.0, sum = 0.0;
    for (int i = 0; i < 16; i++) { sum += term; term *= -a2 / (double)((2 * i + 1) * (2 * i + 2)); }
    return sign * sum;
}
constexpr double c_sinpi(double x) { return c_cospi(x - 0.5); }
constexpr double c_bark(int i) {
    double freq = (double)i * (44100.0 / 512.0);
    double r = freq / 7500.0;
    return 13.0 * c_atan(0.00076 * freq) + 3.5 * c_atan(r * r);
}

// Flat table: win[512] | tw4[3][128] (float2) | cA dA cB dB ath (260 ea)
#define OFF_WIN 0
#define OFF_TW  512                  // float index of tw4 base (768 floats)
#define OFF_CA  1280
#define OFF_DA  1540
#define OFF_CB  1800
#define OFF_DB  2060
#define OFF_ATH 2320
#define TABN4   2580
#define NTW     (3 * 128)            // radix-4 twiddle float2 count

struct AllTabs { alignas(16) float v[TABN4]; };

constexpr AllTabs mk_tabs() {
    AllTabs t{};
    for (int i = 0; i < NFFT; i++)
        t.v[OFF_WIN + i] = (float)(0.5 * (1.0 - c_cospi((double)i / 256.0)));
    for (int r = 0; r < 3; r++)
        for (int j = 0; j < 128; j++) {
            double ang = (double)(j * (r + 1)) / 256.0;      // W512^{j(r+1)} angle/pi
            t.v[OFF_TW + 2 * (r * 128 + j) + 0] = (float)c_cospi(ang);
            t.v[OFF_TW + 2 * (r * 128 + j) + 1] = (float)(-c_sinpi(ang));  // conj
        }
    const double LN10 = 2.30258509299404568402;
    for (int i = 0; i < NBINS; i++) {
        double d = (c_bark(i) - BARKMID) * LN10;
        t.v[OFF_CA + i] = (float)c_exp( 1.7 * d);
        t.v[OFF_DA + i] = (float)c_exp(-1.7 * d);
        t.v[OFF_CB + i] = (float)c_exp(-2.7 * d);
        t.v[OFF_DB + i] = (float)c_exp( 2.7 * d);
        double freq = (double)i * (44100.0 / 512.0);
        double f = freq > 1e-6 ? freq : 1e-6;
        double fk = f / 1000.0;
        double ath_db = 3.64 * c_pow(fk, -0.8)
                      - 6.5 * c_exp(-0.6 * (fk - 3.3) * (fk - 3.3))
                      + 0.001 * fk * fk * fk * fk;
        if (ath_db > 100.0) ath_db = 100.0;
        if (ath_db < -100.0) ath_db = -100.0;
        double a = c_exp(ath_db * 0.1 * LN10);
        if (a < 1e-12) a = 1e-12;
        t.v[OFF_ATH + i] = (float)a;
    }
    return t;
}
__device__ const AllTabs g_tabs = mk_tabs();

// ===========================================================================
__device__ __forceinline__ float2 cadd(float2 a, float2 b) { return make_float2(a.x + b.x, a.y + b.y); }
__device__ __forceinline__ float2 csub(float2 a, float2 b) { return make_float2(a.x - b.x, a.y - b.y); }
__device__ __forceinline__ float2 cmul(float2 a, float2 b) {
    return make_float2(fmaf(a.x, b.x, -a.y * b.y), fmaf(a.x, b.y, a.y * b.x));
}

__device__ __forceinline__ void dft4(float2* x) {
    float2 t0 = cadd(x[0], x[2]), t1 = csub(x[0], x[2]);
    float2 t2 = cadd(x[1], x[3]), t3 = csub(x[1], x[3]);
    x[0] = cadd(t0, t2);
    x[2] = csub(t0, t2);
    x[1] = make_float2(t1.x + t3.y, t1.y - t3.x);   // t1 - i t3
    x[3] = make_float2(t1.x - t3.y, t1.y + t3.x);   // t1 + i t3
}

__device__ __forceinline__ void dft8(float2* x) {
    const float C = 0.70710678118654752f;
    float2 a0 = cadd(x[0], x[4]), a4 = csub(x[0], x[4]);
    float2 a2 = cadd(x[2], x[6]), a6 = csub(x[2], x[6]);
    float2 a1 = cadd(x[1], x[5]), a5 = csub(x[1], x[5]);
    float2 a3 = cadd(x[3], x[7]), a7 = csub(x[3], x[7]);
    float2 b0 = cadd(a0, a2), b2 = csub(a0, a2);
    float2 b1 = cadd(a1, a3), b3 = csub(a1, a3);
    float2 b4 = make_float2(a4.x + a6.y, a4.y - a6.x);
    float2 b6 = make_float2(a4.x - a6.y, a4.y + a6.x);
    float2 b5 = make_float2(a5.x + a7.y, a5.y - a7.x);
    float2 b7 = make_float2(a5.x - a7.y, a5.y + a7.x);
    x[0] = cadd(b0, b1);  x[4] = csub(b0, b1);
    x[2] = make_float2(b2.x + b3.y, b2.y - b3.x);
    x[6] = make_float2(b2.x - b3.y, b2.y + b3.x);
    float2 t5 = make_float2(C * (b5.x + b5.y), C * (b5.y - b5.x));
    x[1] = cadd(b4, t5);  x[5] = csub(b4, t5);
    float2 t7 = make_float2(C * (b7.y - b7.x), -C * (b7.x + b7.y));
    x[3] = cadd(b6, t7);  x[7] = csub(b6, t7);
}

#define PHYS(i) ((i) + ((i) >> 3))
// digit-reversed output position for bin k (radix 4,4,4,8 DIF)
#define POS(k) ((((k) & 3) << 7) | ((((k) >> 2) & 3) << 5) | ((((k) >> 4) & 3) << 3) | ((k) >> 6))
#define BARG(id) asm volatile("bar.sync %0, %1;" :: "r"((id) + 1), "r"(128) : "memory")

__global__ __launch_bounds__(NTHREADS) void pam_kernel(
    const float* __restrict__ pred, const float* __restrict__ tgt,
    float* __restrict__ out)
{
    __shared__ float4 Zs[2][576];               // .xy frame A, .zw frame B (per group)
    __shared__ float2 sTw[NTW];
    __shared__ __align__(16) float pts[NFR][260];
    __shared__ float2 sAtot[2][4], sBtot[2][4];
    __shared__ float redw[8];
    __shared__ int   s_last;

    const int tid  = threadIdx.x;
    const int gid  = tid >> 7;             // group (0/1), 128 threads each
    const int j    = tid & 127;
    const int lane = tid & 31;
    const int wrp  = tid >> 5;             // 0..7
    const int gw   = (tid >> 5) & 3;       // warp within group
    const int fA   = 2 * gid;
    const int fB   = 2 * gid + 1;

    const int b = blockIdx.y;
    const int tb = (NFR * blockIdx.x + 2 * gid) * HOP - (NFFT / 2);

    // ---- stage radix-4 twiddles to shared (3KB, coalesced float4) ----
    {
        const float4* src = (const float4*)&g_tabs.v[OFF_TW];
        float4* dst = (float4*)sTw;
        if (tid < NTW / 2) dst[tid] = src[tid];   // 192 float4
    }

    // ---- window taps: thread j owns n = 4j..4j+3 ----
    const float4 w4 = *(const float4*)&g_tabs.v[OFF_WIN + 4 * j];

    // ---- sample loads (both frames), reflect only in block0/group0 low half ----
    const float* xp = pred + b * LSIG;
    const float* xt = tgt  + b * LSIG;
    float aP[4], aT[4], bP[4], bT[4];
    if (blockIdx.x == 0 && gid == 0 && j < 64) {
        #pragma unroll
        for (int i = 0; i < 4; i++) {
            int g = tb + 4 * j + i;
            if (g < 0) g = -g;
            aP[i] = xp[g]; aT[i] = xt[g];
        }
    } else {
        float4 v1 = *(const float4*)(xp + tb + 4 * j);
        float4 v2 = *(const float4*)(xt + tb + 4 * j);
        aP[0] = v1.x; aP[1] = v1.y; aP[2] = v1.z; aP[3] = v1.w;
        aT[0] = v2.x; aT[1] = v2.y; aT[2] = v2.z; aT[3] = v2.w;
    }
    {
        float4 v1 = *(const float4*)(xp + tb + HOP + 4 * j);
        float4 v2 = *(const float4*)(xt + tb + HOP + 4 * j);
        bP[0] = v1.x; bP[1] = v1.y; bP[2] = v1.z; bP[3] = v1.w;
        bT[0] = v2.x; bT[1] = v2.y; bT[2] = v2.z; bT[3] = v2.w;
    }
    const float wl[4] = { w4.x, w4.y, w4.z, w4.w };
    #pragma unroll
    for (int i = 0; i < 4; i++) {
        int n = 4 * j + i;
        Zs[gid][PHYS(n)] = make_float4(aP[i] * wl[i], aT[i] * wl[i],
                                       bP[i] * wl[i], bT[i] * wl[i]);
    }
    __syncthreads();                       // sTw (block-wide) + Zs ready

    // ---- pass 0: radix-4, stride 128, twiddle tw[r][j] ----
    {
        float2 xa[4], xb[4];
        #pragma unroll
        for (int m = 0; m < 4; m++) {
            float4 v = Zs[gid][PHYS(j + (m << 7))];
            xa[m] = make_float2(v.x, v.y);
            xb[m] = make_float2(v.z, v.w);
        }
        dft4(xa); dft4(xb);
        #pragma unroll
        for (int r = 1; r < 4; r++) {
            float2 w = sTw[(r - 1) * 128 + j];
            xa[r] = cmul(xa[r], w);
            xb[r] = cmul(xb[r], w);
        }
        #pragma unroll
        for (int r = 0; r < 4; r++)
            Zs[gid][PHYS(j + (r << 7))] = make_float4(xa[r].x, xa[r].y, xb[r].x, xb[r].y);
    }
    BARG(gid);

    // ---- pass 1: radix-4 on size-128 blocks, stride 32, twiddle tw[r][4p] ----
    {
        int p = j & 31;
        int base = ((j >> 5) << 7) + p;
        float2 xa[4], xb[4];
        #pragma unroll
        for (int m = 0; m < 4; m++) {
            float4 v = Zs[gid][PHYS(base + (m << 5))];
            xa[m] = make_float2(v.x, v.y);
            xb[m] = make_float2(v.z, v.w);
        }
        dft4(xa); dft4(xb);
        #pragma unroll
        for (int r = 1; r < 4; r++) {
            float2 w = sTw[(r - 1) * 128 + (p << 2)];
            xa[r] = cmul(xa[r], w);
            xb[r] = cmul(xb[r], w);
        }
        #pragma unroll
        for (int r = 0; r < 4; r++)
            Zs[gid][PHYS(base + (r << 5))] = make_float4(xa[r].x, xa[r].y, xb[r].x, xb[r].y);
    }
    BARG(gid);

    // ---- pass 2: radix-4 on size-32 blocks, stride 8, twiddle tw[r][16p] ----
    {
        int p = j & 7;
        int base = ((j >> 3) << 5) + p;
        float2 xa[4], xb[4];
        #pragma unroll
        for (int m = 0; m < 4; m++) {
            float4 v = Zs[gid][PHYS(base + (m << 3))];
            xa[m] = make_float2(v.x, v.y);
            xb[m] = make_float2(v.z, v.w);
        }
        dft4(xa); dft4(xb);
        #pragma unroll
        for (int r = 1; r < 4; r++) {
            float2 w = sTw[(r - 1) * 128 + (p << 4)];
            xa[r] = cmul(xa[r], w);
            xb[r] = cmul(xb[r], w);
        }
        #pragma unroll
        for (int r = 0; r < 4; r++)
            Zs[gid][PHYS(base + (r << 3))] = make_float4(xa[r].x, xa[r].y, xb[r].x, xb[r].y);
    }
    BARG(gid);

    // ---- pass 3: radix-8 on contiguous size-8 blocks (threads 0..63) ----
    if (j < 64) {
        float2 xa[8], xb[8];
        #pragma unroll
        for (int m = 0; m < 8; m++) {
            float4 v = Zs[gid][9 * j + m];      // PHYS(8j+m) = 9j+m
            xa[m] = make_float2(v.x, v.y);
            xb[m] = make_float2(v.z, v.w);
        }
        dft8(xa); dft8(xb);
        #pragma unroll
        for (int m = 0; m < 8; m++)
            Zs[gid][9 * j + m] = make_float4(xa[m].x, xa[m].y, xb[m].x, xb[m].y);
    }
    BARG(gid);

    // ---- psycho tables (2 bins/thread; latency hidden by unpack below) ----
    const float2 cA2 = *(const float2*)&g_tabs.v[OFF_CA  + 2 * j];
    const float2 cB2 = *(const float2*)&g_tabs.v[OFF_CB  + 2 * j];
    const float2 dA2 = *(const float2*)&g_tabs.v[OFF_DA  + 2 * j];
    const float2 dB2 = *(const float2*)&g_tabs.v[OFF_DB  + 2 * j];
    const float2 at2 = *(const float2*)&g_tabs.v[OFF_ATH + 2 * j];
    const float dA256 = g_tabs.v[OFF_DA + 256];
    const float at256 = g_tabs.v[OFF_ATH + 256];

    // ---- unpack both real spectra; bins 2j, 2j+1 ----
    float ppA[2], ptA[2], ppB[2], ptB[2];
    #pragma unroll
    for (int i = 0; i < 2; i++) {
        int k  = 2 * j + i;
        int kc = (NFFT - k) & (NFFT - 1);
        float4 zk = Zs[gid][PHYS(POS(k))];
        float4 zc = Zs[gid][PHYS(POS(kc))];
        {
            float spr = zk.x + zc.x, spi = zk.y - zc.y;
            float str = zk.y + zc.y, sti = zc.x - zk.x;
            ppA[i] = 0.25f * (spr * spr + spi * spi) + 1e-12f;
            ptA[i] = 0.25f * (str * str + sti * sti) + 1e-12f;
        }
        {
            float spr = zk.z + zc.z, spi = zk.w - zc.w;
            float str = zk.w + zc.w, sti = zc.z - zk.z;
            ppB[i] = 0.25f * (spr * spr + spi * spi) + 1e-12f;
            ptB[i] = 0.25f * (str * str + sti * sti) + 1e-12f;
        }
    }
    *(float2*)&pts[fA][2 * j] = make_float2(ptA[0], ptA[1]);
    *(float2*)&pts[fB][2 * j] = make_float2(ptB[0], ptB[1]);

    float ppA6 = 0.f, ptA6 = 0.f, ppB6 = 0.f, ptB6 = 0.f;
    if (j == 127) {                         // bin 256 at POS(256) = 4
        float4 z6 = Zs[gid][PHYS(4)];
        ppA6 = z6.x * z6.x + 1e-12f;  ptA6 = z6.y * z6.y + 1e-12f;
        ppB6 = z6.z * z6.z + 1e-12f;  ptB6 = z6.w * z6.w + 1e-12f;
        pts[fA][256] = ptA6;
        pts[fB][256] = ptB6;
    }
    BARG(gid);

    // ---- tonal detection + scaled linear masker terms ----
    const float cAa[2] = { cA2.x, cA2.y };
    const float cBa[2] = { cB2.x, cB2.y };

    float aAv[2], bAv[2], aBv[2], bBv[2];
    {
        float pprevA = (j == 0) ? 3.4e38f : pts[fA][2 * j - 1];
        float pnextA = pts[fA][2 * j + 2];
        float pprevB = (j == 0) ? 3.4e38f : pts[fB][2 * j - 1];
        float pnextB = pts[fB][2 * j + 2];
        #pragma unroll
        for (int i = 0; i < 2; i++) {
            int k = 2 * j + i;
            float pA = ptA[i];
            float plA = (i == 0) ? pprevA : ptA[0];
            float prA = (i == 1) ? pnextA : ptA[1];
            bool tA = (k >= 1) && (pA > plA) && (pA > prA) && (pA >= 1e-4f);
            aAv[i] = tA ? pA * cAa[i] : 0.0f;
            bAv[i] = tA ? pA * cBa[i] : 0.0f;
            float pB = ptB[i];
            float plB = (i == 0) ? pprevB : ptB[0];
            float prB = (i == 1) ? pnextB : ptB[1];
            bool tB = (k >= 1) && (pB > plB) && (pB > prB) && (pB >= 1e-4f);
            aBv[i] = tB ? pB * cAa[i] : 0.0f;
            bBv[i] = tB ? pB * cBa[i] : 0.0f;
        }
    }

    // local prefix/suffix (2 bins) per frame
    float paA0 = aAv[0], paA1 = fmaxf(paA0, aAv[1]);
    float sbA1 = bAv[1], sbA0 = fmaxf(sbA1, bAv[0]);
    float paB0 = aBv[0], paB1 = fmaxf(paB0, aBv[1]);
    float sbB1 = bBv[1], sbB0 = fmaxf(sbB1, bBv[0]);

    // forward warp-inclusive scan of aggregates (both frames)
    float incA = paA1, incB = paB1;
    #pragma unroll
    for (int off = 1; off < 32; off <<= 1) {
        float oA = __shfl_up_sync(0xffffffffu, incA, off);
        float oB = __shfl_up_sync(0xffffffffu, incB, off);
        if (lane >= off) { incA = fmaxf(incA, oA); incB = fmaxf(incB, oB); }
    }
    float exAA = __shfl_up_sync(0xffffffffu, incA, 1);
    float exAB = __shfl_up_sync(0xffffffffu, incB, 1);
    if (lane == 0) { exAA = 0.0f; exAB = 0.0f; }
    if (lane == 31) sAtot[gid][gw] = make_float2(incA, incB);

    // reverse warp-inclusive scan
    float rincA = sbA0, rincB = sbB0;
    #pragma unroll
    for (int off = 1; off < 32; off <<= 1) {
        float oA = __shfl_down_sync(0xffffffffu, rincA, off);
        float oB = __shfl_down_sync(0xffffffffu, rincB, off);
        if (lane + off < 32) { rincA = fmaxf(rincA, oA); rincB = fmaxf(rincB, oB); }
    }
    float exBA = __shfl_down_sync(0xffffffffu, rincA, 1);
    float exBB = __shfl_down_sync(0xffffffffu, rincB, 1);
    if (lane == 31) { exBA = 0.0f; exBB = 0.0f; }
    if (lane == 0) sBtot[gid][gw] = make_float2(rincA, rincB);
    BARG(gid);

    // combine warp totals across the 4 warps of this group
    #pragma unroll
    for (int w = 0; w < 3; w++) {
        if (w < gw) {
            float2 t = sAtot[gid][w];
            exAA = fmaxf(exAA, t.x);
            exAB = fmaxf(exAB, t.y);
        }
    }
    #pragma unroll
    for (int w = 1; w < 4; w++) {
        if (w > gw) {
            float2 t = sBtot[gid][w];
            exBA = fmaxf(exBA, t.x);
            exBB = fmaxf(exBB, t.y);
        }
    }

    // ---- per-bin masking, weights, error ----
    float ApA[2] = { fmaxf(exAA, paA0), fmaxf(exAA, paA1) };
    float BsA[2] = { fmaxf(exBA, sbA0), fmaxf(exBA, sbA1) };
    float ApB[2] = { fmaxf(exAB, paB0), fmaxf(exAB, paB1) };
    float BsB[2] = { fmaxf(exBB, sbB0), fmaxf(exBB, sbB1) };

    const float dAa[2] = { dA2.x, dA2.y };
    const float dBa[2] = { dB2.x, dB2.y };
    const float ata[2] = { at2.x, at2.y };

    float contrib = 0.0f;
    #pragma unroll
    for (int i = 0; i < 2; i++) {
        {
            float masking = fmaxf(ApA[i] * dAa[i], BsA[i] * dBa[i]);
            float combined = masking + ata[i];
            float w  = __log10f(ptA[i] / (combined + 1e-12f) + 1.0f);
            float d  = sqrtf(ppA[i]) - sqrtf(ptA[i]);
            contrib += w * d * d;
        }
        {
            float masking = fmaxf(ApB[i] * dAa[i], BsB[i] * dBa[i]);
            float combined = masking + ata[i];
            float w  = __log10f(ptB[i] / (combined + 1e-12f) + 1.0f);
            float d  = sqrtf(ppB[i]) - sqrtf(ptB[i]);
            contrib += w * d * d;
        }
    }
    if (j == 127) {                         // bin 256: never tonal, A-side only
        {
            float combined = ApA[1] * dA256 + at256;
            float w  = __log10f(ptA6 / (combined + 1e-12f) + 1.0f);
            float d  = sqrtf(ppA6) - sqrtf(ptA6);
            contrib += w * d * d;
        }
        {
            float combined = ApB[1] * dA256 + at256;
            float w  = __log10f(ptB6 / (combined + 1e-12f) + 1.0f);
            float d  = sqrtf(ppB6) - sqrtf(ptB6);
            contrib += w * d * d;
        }
    }

    // ---- block reduction (8 warps) ----
    float v = contrib;
    #pragma unroll
    for (int off = 16; off > 0; off >>= 1)
        v += __shfl_down_sync(0xffffffffu, v, off);
    if (lane == 0) redw[wrp] = v;
    __syncthreads();
    const int bid = blockIdx.y * (NT / NFR) + blockIdx.x;
    if (tid == 0) {
        float s = redw[0];
        #pragma unroll
        for (int q = 1; q < 8; q++) s += redw[q];
        g_partial[bid] = s;
    }

    // ---- last block: deterministic global reduction ----
    __threadfence();
    if (tid == 0) {
        unsigned r = atomicAdd(&g_count, 1u);
        s_last = (r == NBLKS - 1) ? 1 : 0;
    }
    __syncthreads();
    if (s_last) {
        float s = 0.0f;
        for (int i = tid; i < NBLKS; i += NTHREADS) s += g_partial[i];
        #pragma unroll
        for (int off = 16; off > 0; off >>= 1)
            s += __shfl_down_sync(0xffffffffu, s, off);
        if (lane == 0) redw[wrp] = s;
        __syncthreads();
        if (tid == 0) {
            float s2 = redw[0];
            #pragma unroll
            for (int q = 1; q < 8; q++) s2 += redw[q];
            out[0] = s2 * (1.0f / (float)(BATCH * NBINS * NT));
            g_count = 0;
        }
    }
}

extern "C" void kernel_launch(void* const* d_in, const int* in_sizes, int n_in,
                              void* d_out, int out_size) {
    const float* pred = (const float*)d_in[0];
    const float* tgt  = (const float*)d_in[1];
    float* out = (float*)d_out;
    dim3 grid(NT / NFR, BATCH);
    pam_kernel<<<grid, NTHREADS>>>(pred, tgt, out);
}

// round 16
// speedup vs baseline: 1.1327x; 1.1327x over previous
#include <cuda_runtime.h>
#include <math.h>

#define NFFT   512
#define HOP    480
#define NBINS  257
#define BATCH  8
#define LSIG   88200
#define NT     184
#define NFR    4                      // frames per block = warps per block
#define NTHREADS 128
#define NBLKS  (BATCH * NT / NFR)     // 368 blocks
#define BARKMID 12.37
#define FULLM  0xffffffffu

__device__ float g_partial[NBLKS];
__device__ unsigned int g_count = 0;

// ===========================================================================
// constexpr fp64 math (compile-time)
// ===========================================================================
constexpr double c_sqrt(double x) {
    double g = x > 1.0 ? x : 1.0;
    for (int i = 0; i < 80; i++) g = 0.5 * (g + x / g);
    return g;
}
constexpr double c_exp(double x) {
    const double ln2 = 0.69314718055994530942;
    int k = (int)(x / ln2 + (x >= 0 ? 0.5 : -0.5));
    double r = x - (double)k * ln2;
    double term = 1.0, sum = 1.0;
    for (int i = 1; i <= 22; i++) { term *= r / (double)i; sum += term; }
    double p = 1.0;
    if (k >= 0) { for (int i = 0; i < k;  i++) p *= 2.0; }
    else        { for (int i = 0; i < -k; i++) p *= 0.5; }
    return sum * p;
}
constexpr double c_log(double x) {
    int k = 0; double m = x;
    while (m >= 2.0) { m *= 0.5; k++; }
    while (m < 1.0)  { m *= 2.0; k--; }
    double t = (m - 1.0) / (m + 1.0), t2 = t * t, term = t, sum = 0.0;
    for (int i = 0; i < 45; i++) { sum += term / (double)(2 * i + 1); term *= t2; }
    return 2.0 * sum + (double)k * 0.69314718055994530942;
}
constexpr double c_pow(double x, double y) { return c_exp(y * c_log(x)); }
constexpr double c_atan(double x) {
    if (x < 0.0) return -c_atan(-x);
    if (x > 1.0) return 1.57079632679489661923 - c_atan(1.0 / x);
    double x1 = x  / (1.0 + c_sqrt(1.0 + x  * x));
    double x2 = x1 / (1.0 + c_sqrt(1.0 + x1 * x1));
    double t2 = x2 * x2, term = x2, sum = 0.0;
    for (int i = 0; i < 26; i++) {
        sum += ((i & 1) ? -term : term) / (double)(2 * i + 1);
        term *= t2;
    }
    return 4.0 * sum;
}
constexpr double c_cospi(double x) {
    double y = x;
    while (y >= 2.0) y -= 2.0;
    while (y < 0.0)  y += 2.0;
    double sign = 1.0;
    if (y > 1.0) y = 2.0 - y;
    if (y > 0.5) { y = 1.0 - y; sign = -1.0; }
    double a = y * 3.14159265358979323846;
    double a2 = a * a, term = 1.0, sum = 0.0;
    for (int i = 0; i < 16; i++) { sum += term; term *= -a2 / (double)((2 * i + 1) * (2 * i + 2)); }
    return sign * sum;
}
constexpr double c_bark(int i) {
    double freq = (double)i * (44100.0 / 512.0);
    double r = freq / 7500.0;
    return 13.0 * c_atan(0.00076 * freq) + 3.5 * c_atan(r * r);
}

// Flat table: win[512] | cA dA cB dB ath (260 each)
#define OFF_WIN 0
#define OFF_CA  512
#define OFF_DA  772
#define OFF_CB  1032
#define OFF_DB  1292
#define OFF_ATH 1552
#define TABN4   1812

struct AllTabs { alignas(16) float v[TABN4]; };

constexpr AllTabs mk_tabs() {
    AllTabs t{};
    for (int i = 0; i < NFFT; i++)
        t.v[OFF_WIN + i] = (float)(0.5 * (1.0 - c_cospi((double)i / 256.0)));
    const double LN10 = 2.30258509299404568402;
    for (int i = 0; i < NBINS; i++) {
        double d = (c_bark(i) - BARKMID) * LN10;
        t.v[OFF_CA + i] = (float)c_exp( 1.7 * d);
        t.v[OFF_DA + i] = (float)c_exp(-1.7 * d);
        t.v[OFF_CB + i] = (float)c_exp(-2.7 * d);
        t.v[OFF_DB + i] = (float)c_exp( 2.7 * d);
        double freq = (double)i * (44100.0 / 512.0);
        double f = freq > 1e-6 ? freq : 1e-6;
        double fk = f / 1000.0;
        double ath_db = 3.64 * c_pow(fk, -0.8)
                      - 6.5 * c_exp(-0.6 * (fk - 3.3) * (fk - 3.3))
                      + 0.001 * fk * fk * fk * fk;
        if (ath_db > 100.0) ath_db = 100.0;
        if (ath_db < -100.0) ath_db = -100.0;
        double a = c_exp(ath_db * 0.1 * LN10);
        if (a < 1e-12) a = 1e-12;
        t.v[OFF_ATH + i] = (float)a;
    }
    return t;
}
__device__ const AllTabs g_tabs = mk_tabs();

// ===========================================================================
__device__ __forceinline__ float2 cadd(float2 a, float2 b) { return make_float2(a.x + b.x, a.y + b.y); }
__device__ __forceinline__ float2 csub(float2 a, float2 b) { return make_float2(a.x - b.x, a.y - b.y); }
__device__ __forceinline__ float2 cmul(float2 a, float2 b) {
    return make_float2(fmaf(a.x, b.x, -a.y * b.y), fmaf(a.x, b.y, a.y * b.x));
}
__device__ __forceinline__ float2 csq(float2 a) {
    return make_float2(a.x * a.x - a.y * a.y, 2.0f * a.x * a.y);
}
__device__ __forceinline__ float2 mul_negi(float2 a) { return make_float2(a.y, -a.x); }
__device__ __forceinline__ float2 cneg(float2 a) { return make_float2(-a.x, -a.y); }
__device__ __forceinline__ float2 shflx(float2 v, int m) {
    return make_float2(__shfl_xor_sync(FULLM, v.x, m),
                       __shfl_xor_sync(FULLM, v.y, m));
}

// 4-pt DFT: out[d] = sum_a in[a] * W4^{ad},  W4 = -i
__device__ __forceinline__ void dft4(float2* x) {
    float2 t0 = cadd(x[0], x[2]), t1 = csub(x[0], x[2]);
    float2 t2 = cadd(x[1], x[3]), t3 = csub(x[1], x[3]);
    x[0] = cadd(t0, t2);
    x[2] = csub(t0, t2);
    x[1] = make_float2(t1.x + t3.y, t1.y - t3.x);   // t1 - i t3
    x[3] = make_float2(t1.x - t3.y, t1.y + t3.x);   // t1 + i t3
}

#define SL(r) ((((r) & 3) << 2) | ((r) >> 2))      // 4-bit digit swap (involution)

__global__ __launch_bounds__(NTHREADS) void pam_kernel(
    const float* __restrict__ pred, const float* __restrict__ tgt,
    float* __restrict__ out)
{
    __shared__ float2 sPt[NFR][32];
    __shared__ float2 sAg[NFR][32];
    __shared__ float2 sEx[NFR][32];
    __shared__ float  redw[NFR];
    __shared__ int    s_last;

    const int tid = threadIdx.x;
    const int wrp = tid >> 5;              // warp = frame
    const int p   = tid & 31;

    const int b  = blockIdx.y;
    const int tf = NFR * blockIdx.x + wrp; // frame index (time)
    const int tb = tf * HOP - 256;

    const float* xp = pred + b * LSIG;
    const float* xt = tgt  + b * LSIG;

    // ---- load + window: lane p holds x[p + 32m], m = 0..15 ----
    float2 z[16];
    if (tf == 0) {
        #pragma unroll
        for (int m = 0; m < 16; m++) {
            int n = p + 32 * m;
            int g = tb + n; if (g < 0) g = -g;
            float w = g_tabs.v[OFF_WIN + n];
            z[m] = make_float2(xp[g] * w, xt[g] * w);
        }
    } else {
        #pragma unroll
        for (int m = 0; m < 16; m++) {
            int n = p + 32 * m;
            float w = g_tabs.v[OFF_WIN + n];
            z[m] = make_float2(xp[tb + n] * w, xt[tb + n] * w);
        }
    }

    // ---- twiddle powers w^r, w = W512^p ----
    float sn, cs;
    sincospif((float)p * (1.0f / 256.0f), &sn, &cs);
    float2 w1 = make_float2(cs, -sn);
    float2 w2 = csq(w1), w4 = csq(w2), w8 = csq(w4), w16 = csq(w8);
    float2 w3 = cmul(w2, w1), w5 = cmul(w4, w1), w6 = cmul(w4, w2), w7 = cmul(w4, w3);
    float2 w9 = cmul(w8, w1), w10 = cmul(w8, w2), w11 = cmul(w8, w3), w12 = cmul(w8, w4);
    float2 w13 = cmul(w8, w5), w14 = cmul(w8, w6), w15 = cmul(w8, w7);

    // ---- stage A: 16-pt DFT over m (radix 4x4) ----
    #pragma unroll
    for (int bb = 0; bb < 4; bb++) {
        float2 q[4] = { z[bb], z[bb + 4], z[bb + 8], z[bb + 12] };
        dft4(q);
        z[bb] = q[0]; z[bb + 4] = q[1]; z[bb + 8] = q[2]; z[bb + 12] = q[3];
    }
    {
        const float C1 = 0.92387953251128674f, S1 = 0.38268343236508977f;
        const float Hh = 0.70710678118654752f;
        z[5]  = cmul(z[5],  make_float2( C1, -S1));   // W16^1
        z[6]  = cmul(z[6],  make_float2( Hh, -Hh));   // W16^2
        z[7]  = cmul(z[7],  make_float2( S1, -C1));   // W16^3
        z[9]  = cmul(z[9],  make_float2( Hh, -Hh));   // W16^2
        z[10] = mul_negi(z[10]);                      // W16^4
        z[11] = cmul(z[11], make_float2(-Hh, -Hh));   // W16^6
        z[13] = cmul(z[13], make_float2( S1, -C1));   // W16^3
        z[14] = cmul(z[14], make_float2(-Hh, -Hh));   // W16^6
        z[15] = cmul(z[15], make_float2(-C1,  S1));   // W16^9
    }
    #pragma unroll
    for (int d = 0; d < 4; d++) {
        float2 q[4] = { z[4 * d], z[4 * d + 1], z[4 * d + 2], z[4 * d + 3] };
        dft4(q);
        z[4 * d] = q[0]; z[4 * d + 1] = q[1]; z[4 * d + 2] = q[2]; z[4 * d + 3] = q[3];
    }
    z[1]  = cmul(z[1],  w4);  z[2]  = cmul(z[2],  w8);  z[3]  = cmul(z[3],  w12);
    z[4]  = cmul(z[4],  w1);  z[5]  = cmul(z[5],  w5);  z[6]  = cmul(z[6],  w9);
    z[7]  = cmul(z[7],  w13); z[8]  = cmul(z[8],  w2);  z[9]  = cmul(z[9],  w6);
    z[10] = cmul(z[10], w10); z[11] = cmul(z[11], w14); z[12] = cmul(z[12], w3);
    z[13] = cmul(z[13], w7);  z[14] = cmul(z[14], w11); z[15] = cmul(z[15], w15);

    // ---- stage B: 32-pt DFT across lanes per r (radix-2 DIF, shuffles) ----
    const float Hh = 0.70710678118654752f;
    float2 T2 = cneg(csq(w16));              // = W16^{p&7} on high-branch lanes
    int pm3 = p & 3;
    float2 T3 = (pm3 == 0) ? make_float2(1.f, 0.f) :
                (pm3 == 1) ? make_float2(Hh, -Hh)  :
                (pm3 == 2) ? make_float2(0.f, -1.f) : make_float2(-Hh, -Hh);

    #pragma unroll
    for (int r = 0; r < 16; r++) {
        const int s = SL(r);
        float2 d = z[s];
        float2 e = shflx(d, 16);
        d = (p & 16) ? cmul(csub(d, e), w16) : cadd(d, e);
        e = shflx(d, 8);
        d = (p & 8) ? cmul(csub(e, d), T2) : cadd(d, e);
        e = shflx(d, 4);
        d = (p & 4) ? cmul(csub(e, d), T3) : cadd(d, e);
        e = shflx(d, 2);
        {
            float2 df = csub(e, d);
            float2 tw = (p & 1) ? make_float2(df.y, -df.x) : df;
            d = (p & 2) ? tw : cadd(d, e);
        }
        e = shflx(d, 1);
        d = (p & 1) ? csub(e, d) : cadd(d, e);
        z[s] = d;                            // Z[16*br5(p) + r]
    }

    // ---- bin bookkeeping ----
    const int t5 = (int)(__brev((unsigned)p) >> 27);       // br5(p)
    const bool ev = !(p & 1);
    const int tch = ev ? t5 : 31 - t5;
    const int h   = 2 * tch + (p & 1);                     // half-chunk 0..31
    const int kb  = 8 * h;                                 // first bin

    // ---- unpack: conjugate data from partner lane p^31 ----
    float2 zr[8];
    #pragma unroll
    for (int q = 0; q < 8; q++) {
        const int s = SL(8 + q);
        zr[q].x = __shfl_sync(FULLM, z[s].x, p ^ 31);
        zr[q].y = __shfl_sync(FULLM, z[s].y, p ^ 31);
    }
    const int pc0 = (int)(__brev((unsigned)((32 - t5) & 31)) >> 27);
    float2 zc0;
    zc0.x = __shfl_sync(FULLM, z[0].x, pc0);               // SL(0)=0
    zc0.y = __shfl_sync(FULLM, z[0].y, pc0);

    float pp[8], pt[8];
    #pragma unroll
    for (int i = 0; i < 8; i++) {
        float2 zk, zc;
        if (i == 0) { zk = ev ? z[SL(0)] : zr[0];  zc = ev ? zc0 : z[SL(8)]; }
        else {
            zk = ev ? z[SL(i)] : zr[i];
            zc = ev ? zr[8 - i] : z[SL(8 - i)];
        }
        float spr = zk.x + zc.x, spi = zk.y - zc.y;
        float str = zk.y + zc.y, sti = zc.x - zk.x;
        pp[i] = 0.25f * (spr * spr + spi * spi) + 1e-12f;
        pt[i] = 0.25f * (str * str + sti * sti) + 1e-12f;
    }

    float pp6 = 0.f, pt6 = 0.f;
    if (p == 1) {                           // lane 1 reg 0 = Z[256]
        float2 z6 = z[0];
        pp6 = z6.x * z6.x + 1e-12f;
        pt6 = z6.y * z6.y + 1e-12f;
    }

    // ---- psycho tables for bins kb..kb+7 ----
    const float4 cAl = *(const float4*)&g_tabs.v[OFF_CA + kb];
    const float4 cAh = *(const float4*)&g_tabs.v[OFF_CA + kb + 4];
    const float4 cBl = *(const float4*)&g_tabs.v[OFF_CB + kb];
    const float4 cBh = *(const float4*)&g_tabs.v[OFF_CB + kb + 4];
    const float4 dAl = *(const float4*)&g_tabs.v[OFF_DA + kb];
    const float4 dAh = *(const float4*)&g_tabs.v[OFF_DA + kb + 4];
    const float4 dBl = *(const float4*)&g_tabs.v[OFF_DB + kb];
    const float4 dBh = *(const float4*)&g_tabs.v[OFF_DB + kb + 4];
    const float4 atl = *(const float4*)&g_tabs.v[OFF_ATH + kb];
    const float4 ath = *(const float4*)&g_tabs.v[OFF_ATH + kb + 4];
    const float cAv[8] = { cAl.x, cAl.y, cAl.z, cAl.w, cAh.x, cAh.y, cAh.z, cAh.w };
    const float cBv[8] = { cBl.x, cBl.y, cBl.z, cBl.w, cBh.x, cBh.y, cBh.z, cBh.w };
    const float dAv[8] = { dAl.x, dAl.y, dAl.z, dAl.w, dAh.x, dAh.y, dAh.z, dAh.w };
    const float dBv[8] = { dBl.x, dBl.y, dBl.z, dBl.w, dBh.x, dBh.y, dBh.z, dBh.w };
    const float atv[8] = { atl.x, atl.y, atl.z, atl.w, ath.x, ath.y, ath.z, ath.w };
    const float dA256 = g_tabs.v[OFF_DA + 256];
    const float at256 = g_tabs.v[OFF_ATH + 256];

    // ---- boundary pt exchange (warp-local smem) ----
    sPt[wrp][h] = make_float2(pt[0], pt[7]);
    __syncwarp();
    float prevLast  = sPt[wrp][(h - 1) & 31].y;
    float nextFirst = sPt[wrp][(h + 1) & 31].x;
    if (h == 0)  prevLast  = 3.4e38f;
    if (h == 31) nextFirst = pt6;           // h=31 is lane 1, pt6 local

    // ---- tonal + scaled linear masker terms ----
    float av[8], bv[8];
    #pragma unroll
    for (int i = 0; i < 8; i++) {
        int k = kb + i;
        float pl = i ? pt[i - 1] : prevLast;
        float pr = (i < 7) ? pt[i + 1] : nextFirst;
        bool tn = (k >= 1) && (pt[i] > pl) && (pt[i] > pr) && (pt[i] >= 1e-4f);
        av[i] = tn ? pt[i] * cAv[i] : 0.0f;
        bv[i] = tn ? pt[i] * cBv[i] : 0.0f;
    }
    float pa[8], sb[8];
    pa[0] = av[0];
    #pragma unroll
    for (int i = 1; i < 8; i++) pa[i] = fmaxf(pa[i - 1], av[i]);
    sb[7] = bv[7];
    #pragma unroll
    for (int i = 6; i >= 0; i--) sb[i] = fmaxf(sb[i + 1], bv[i]);

    // ---- cross-chunk scans (permuted via smem, then lane-order shfl scan) ----
    sAg[wrp][h] = make_float2(pa[7], sb[0]);
    __syncwarp();
    float2 vag = sAg[wrp][p];               // lane l <- aggregate of half-chunk l
    float ia = vag.x, ib = vag.y;
    #pragma unroll
    for (int off = 1; off < 32; off <<= 1) {
        float oa = __shfl_up_sync(FULLM, ia, off);
        float ob = __shfl_down_sync(FULLM, ib, off);
        if (p >= off)      ia = fmaxf(ia, oa);
        if (p + off < 32)  ib = fmaxf(ib, ob);
    }
    float exA = __shfl_up_sync(FULLM, ia, 1);   if (p == 0)  exA = 0.0f;
    float exB = __shfl_down_sync(FULLM, ib, 1); if (p == 31) exB = 0.0f;
    sEx[wrp][p] = make_float2(exA, exB);
    __syncwarp();
    float2 ex = sEx[wrp][h];

    // ---- per-bin masking, weights, error ----
    float contrib = 0.0f;
    #pragma unroll
    for (int i = 0; i < 8; i++) {
        float Ap = fmaxf(ex.x, pa[i]);
        float Bs = fmaxf(ex.y, sb[i]);
        float masking = fmaxf(Ap * dAv[i], Bs * dBv[i]);
        float combined = masking + atv[i];
        float w  = __log10f(pt[i] / (combined + 1e-12f) + 1.0f);
        float d  = sqrtf(pp[i]) - sqrtf(pt[i]);
        contrib += w * d * d;
    }
    if (p == 1) {                           // bin 256: never tonal, A-side only
        float Ap = fmaxf(ex.x, pa[7]);      // prefix over all bins <= 255
        float combined = Ap * dA256 + at256;
        float w  = __log10f(pt6 / (combined + 1e-12f) + 1.0f);
        float d  = sqrtf(pp6) - sqrtf(pt6);
        contrib += w * d * d;
    }

    // ---- block reduction (4 independent warps meet here) ----
    float v = contrib;
    #pragma unroll
    for (int off = 16; off > 0; off >>= 1)
        v += __shfl_down_sync(FULLM, v, off);
    if (p == 0) redw[wrp] = v;
    __syncthreads();
    const int bid = blockIdx.y * (NT / NFR) + blockIdx.x;
    if (tid == 0)
        g_partial[bid] = redw[0] + redw[1] + redw[2] + redw[3];

    // ---- last block: deterministic global reduction ----
    __threadfence();
    if (tid == 0) {
        unsigned r = atomicAdd(&g_count, 1u);
        s_last = (r == NBLKS - 1) ? 1 : 0;
    }
    __syncthreads();
    if (s_last) {
        float s = 0.0f;
        for (int i = tid; i < NBLKS; i += NTHREADS) s += g_partial[i];
        #pragma unroll
        for (int off = 16; off > 0; off >>= 1)
            s += __shfl_down_sync(FULLM, s, off);
        if (p == 0) redw[wrp] = s;
        __syncthreads();
        if (tid == 0) {
            out[0] = (redw[0] + redw[1] + redw[2] + redw[3])
                   * (1.0f / (float)(BATCH * NBINS * NT));
            g_count = 0;
        }
    }
}

extern "C" void kernel_launch(void* const* d_in, const int* in_sizes, int n_in,
                              void* d_out, int out_size) {
    const float* pred = (const float*)d_in[0];
    const float* tgt  = (const float*)d_in[1];
    float* out = (float*)d_out;
    dim3 grid(NT / NFR, BATCH);
    pam_kernel<<<grid, NTHREADS>>>(pred, tgt, out);
}

// round 17
// speedup vs baseline: 1.1414x; 1.0077x over previous
#include <cuda_runtime.h>
#include <math.h>

#define NFFT   512
#define HOP    480
#define NBINS  257
#define BATCH  8
#define LSIG   88200
#define NT     184
#define NFR    4                      // frames per block, 64 threads each
#define NTHREADS 256
#define NBLKS  (BATCH * NT / NFR)     // 368 blocks
#define BARKMID 12.37
#define FULLM  0xffffffffu

__device__ float g_partial[NBLKS];
__device__ unsigned int g_count = 0;

// ===========================================================================
// constexpr fp64 math (compile-time)
// ===========================================================================
constexpr double c_sqrt(double x) {
    double g = x > 1.0 ? x : 1.0;
    for (int i = 0; i < 80; i++) g = 0.5 * (g + x / g);
    return g;
}
constexpr double c_exp(double x) {
    const double ln2 = 0.69314718055994530942;
    int k = (int)(x / ln2 + (x >= 0 ? 0.5 : -0.5));
    double r = x - (double)k * ln2;
    double term = 1.0, sum = 1.0;
    for (int i = 1; i <= 22; i++) { term *= r / (double)i; sum += term; }
    double p = 1.0;
    if (k >= 0) { for (int i = 0; i < k;  i++) p *= 2.0; }
    else        { for (int i = 0; i < -k; i++) p *= 0.5; }
    return sum * p;
}
constexpr double c_log(double x) {
    int k = 0; double m = x;
    while (m >= 2.0) { m *= 0.5; k++; }
    while (m < 1.0)  { m *= 2.0; k--; }
    double t = (m - 1.0) / (m + 1.0), t2 = t * t, term = t, sum = 0.0;
    for (int i = 0; i < 45; i++) { sum += term / (double)(2 * i + 1); term *= t2; }
    return 2.0 * sum + (double)k * 0.69314718055994530942;
}
constexpr double c_pow(double x, double y) { return c_exp(y * c_log(x)); }
constexpr double c_atan(double x) {
    if (x < 0.0) return -c_atan(-x);
    if (x > 1.0) return 1.57079632679489661923 - c_atan(1.0 / x);
    double x1 = x  / (1.0 + c_sqrt(1.0 + x  * x));
    double x2 = x1 / (1.0 + c_sqrt(1.0 + x1 * x1));
    double t2 = x2 * x2, term = x2, sum = 0.0;
    for (int i = 0; i < 26; i++) {
        sum += ((i & 1) ? -term : term) / (double)(2 * i + 1);
        term *= t2;
    }
    return 4.0 * sum;
}
constexpr double c_cospi(double x) {
    double y = x;
    while (y >= 2.0) y -= 2.0;
    while (y < 0.0)  y += 2.0;
    double sign = 1.0;
    if (y > 1.0) y = 2.0 - y;
    if (y > 0.5) { y = 1.0 - y; sign = -1.0; }
    double a = y * 3.14159265358979323846;
    double a2 = a * a, term = 1.0, sum = 0.0;
    for (int i = 0; i < 16; i++) { sum += term; term *= -a2 / (double)((2 * i + 1) * (2 * i + 2)); }
    return sign * sum;
}
constexpr double c_bark(int i) {
    double freq = (double)i * (44100.0 / 512.0);
    double r = freq / 7500.0;
    return 13.0 * c_atan(0.00076 * freq) + 3.5 * c_atan(r * r);
}

// Flat table: win[512] | cA dA cB dB ath (260 each)
#define OFF_WIN 0
#define OFF_CA  512
#define OFF_DA  772
#define OFF_CB  1032
#define OFF_DB  1292
#define OFF_ATH 1552
#define TABN4   1812

struct AllTabs { alignas(16) float v[TABN4]; };

constexpr AllTabs mk_tabs() {
    AllTabs t{};
    for (int i = 0; i < NFFT; i++)
        t.v[OFF_WIN + i] = (float)(0.5 * (1.0 - c_cospi((double)i / 256.0)));
    const double LN10 = 2.30258509299404568402;
    for (int i = 0; i < NBINS; i++) {
        double d = (c_bark(i) - BARKMID) * LN10;
        t.v[OFF_CA + i] = (float)c_exp( 1.7 * d);
        t.v[OFF_DA + i] = (float)c_exp(-1.7 * d);
        t.v[OFF_CB + i] = (float)c_exp(-2.7 * d);
        t.v[OFF_DB + i] = (float)c_exp( 2.7 * d);
        double freq = (double)i * (44100.0 / 512.0);
        double f = freq > 1e-6 ? freq : 1e-6;
        double fk = f / 1000.0;
        double ath_db = 3.64 * c_pow(fk, -0.8)
                      - 6.5 * c_exp(-0.6 * (fk - 3.3) * (fk - 3.3))
                      + 0.001 * fk * fk * fk * fk;
        if (ath_db > 100.0) ath_db = 100.0;
        if (ath_db < -100.0) ath_db = -100.0;
        double a = c_exp(ath_db * 0.1 * LN10);
        if (a < 1e-12) a = 1e-12;
        t.v[OFF_ATH + i] = (float)a;
    }
    return t;
}
__device__ const AllTabs g_tabs = mk_tabs();

// ===========================================================================
__device__ __forceinline__ float2 cadd(float2 a, float2 b) { return make_float2(a.x + b.x, a.y + b.y); }
__device__ __forceinline__ float2 csub(float2 a, float2 b) { return make_float2(a.x - b.x, a.y - b.y); }
__device__ __forceinline__ float2 cmul(float2 a, float2 b) {
    return make_float2(fmaf(a.x, b.x, -a.y * b.y), fmaf(a.x, b.y, a.y * b.x));
}
__device__ __forceinline__ float2 csq(float2 a) {
    return make_float2(a.x * a.x - a.y * a.y, 2.0f * a.x * a.y);
}
__device__ __forceinline__ float2 cneg(float2 a) { return make_float2(-a.x, -a.y); }
__device__ __forceinline__ float2 shflx(float2 v, int m) {
    return make_float2(__shfl_xor_sync(FULLM, v.x, m),
                       __shfl_xor_sync(FULLM, v.y, m));
}

// 8-pt DFT, natural in/out order
__device__ __forceinline__ void dft8(float2* x) {
    const float C = 0.70710678118654752f;
    float2 a0 = cadd(x[0], x[4]), a4 = csub(x[0], x[4]);
    float2 a2 = cadd(x[2], x[6]), a6 = csub(x[2], x[6]);
    float2 a1 = cadd(x[1], x[5]), a5 = csub(x[1], x[5]);
    float2 a3 = cadd(x[3], x[7]), a7 = csub(x[3], x[7]);
    float2 b0 = cadd(a0, a2), b2 = csub(a0, a2);
    float2 b1 = cadd(a1, a3), b3 = csub(a1, a3);
    float2 b4 = make_float2(a4.x + a6.y, a4.y - a6.x);
    float2 b6 = make_float2(a4.x - a6.y, a4.y + a6.x);
    float2 b5 = make_float2(a5.x + a7.y, a5.y - a7.x);
    float2 b7 = make_float2(a5.x - a7.y, a5.y + a7.x);
    x[0] = cadd(b0, b1);  x[4] = csub(b0, b1);
    x[2] = make_float2(b2.x + b3.y, b2.y - b3.x);
    x[6] = make_float2(b2.x - b3.y, b2.y + b3.x);
    float2 t5 = make_float2(C * (b5.x + b5.y), C * (b5.y - b5.x));
    x[1] = cadd(b4, t5);  x[5] = csub(b4, t5);
    float2 t7 = make_float2(C * (b7.y - b7.x), -C * (b7.x + b7.y));
    x[3] = cadd(b6, t7);  x[7] = csub(b6, t7);
}

#define PH(i) ((i) + ((i) >> 3))                   // pad for 512-bin smem array
#define BARF(id) asm volatile("bar.sync %0, %1;" :: "r"((id) + 1), "r"(64) : "memory")

__global__ __launch_bounds__(NTHREADS) void pam_kernel(
    const float* __restrict__ pred, const float* __restrict__ tgt,
    float* __restrict__ out)
{
    __shared__ float2 sX[NFR][576];                // Y exchange, then X bins
    __shared__ float  sAg[NFR], sBg[NFR];
    __shared__ float  redw[8];
    __shared__ int    s_last;

    const int tid  = threadIdx.x;
    const int grp  = tid >> 6;             // frame group (0..3)
    const int t    = tid & 63;             // thread within frame
    const int p    = t & 31;               // lane
    const int hw   = t >> 5;               // warp half within frame
    const int lane = p;
    const int wrp  = tid >> 5;             // block warp 0..7

    const int b  = blockIdx.y;
    const int tf = NFR * blockIdx.x + grp;
    const int tb = tf * HOP - 256;

    const float* xp = pred + b * LSIG;
    const float* xt = tgt  + b * LSIG;

    // ---- load + window: thread t holds x[t + 64m], m = 0..7 ----
    float2 z[8];
    if (tf == 0) {
        #pragma unroll
        for (int m = 0; m < 8; m++) {
            int n = t + 64 * m;
            int g = tb + n; if (g < 0) g = -g;
            float w = g_tabs.v[OFF_WIN + n];
            z[m] = make_float2(xp[g] * w, xt[g] * w);
        }
    } else {
        #pragma unroll
        for (int m = 0; m < 8; m++) {
            int n = t + 64 * m;
            float w = g_tabs.v[OFF_WIN + n];
            z[m] = make_float2(xp[tb + n] * w, xt[tb + n] * w);
        }
    }

    // ---- twiddles: w = W512^t, powers w^1..w^8; in-warp bases ----
    float sn, cs;
    sincospif((float)t * (1.0f / 256.0f), &sn, &cs);
    float2 w1 = make_float2(cs, -sn);
    float2 w2 = csq(w1), w4 = csq(w2), w8 = csq(w4);
    float2 w3 = cmul(w2, w1), w5 = cmul(w4, w1), w6 = csq(w3), w7 = cmul(w4, w3);
    float2 W32p = csq(w8);                 // = W32^p for both warp halves
    float2 T2 = cneg(csq(W32p));           // = W16^{p&7} on high-branch lanes
    const float Hh = 0.70710678118654752f;
    int pm3 = p & 3;
    float2 T3 = (pm3 == 0) ? make_float2(1.f, 0.f) :
                (pm3 == 1) ? make_float2(Hh, -Hh)  :
                (pm3 == 2) ? make_float2(0.f, -1.f) : make_float2(-Hh, -Hh);

    // ---- stage A: 8-pt DFT over m + twiddle w^d ----
    dft8(z);
    z[1] = cmul(z[1], w1);  z[2] = cmul(z[2], w2);  z[3] = cmul(z[3], w3);
    z[4] = cmul(z[4], w4);  z[5] = cmul(z[5], w5);  z[6] = cmul(z[6], w6);
    z[7] = cmul(z[7], w7);

    // ---- 64-pt DFT over t: level 1 cross-warp via smem ----
    #pragma unroll
    for (int d = 0; d < 8; d++) sX[grp][9 * t + d] = z[d];
    BARF(grp);
    {
        const int tp = t ^ 32;
        float2 e[8];
        #pragma unroll
        for (int d = 0; d < 8; d++) e[d] = sX[grp][9 * tp + d];
        #pragma unroll
        for (int d = 0; d < 8; d++)
            z[d] = hw ? cmul(csub(z[d], e[d]), w8) : cadd(z[d], e[d]);
    }

    // ---- remaining 32-pt DFT in-warp: 5 shfl levels, level-order ILP ----
    #pragma unroll
    for (int d = 0; d < 8; d++) {
        float2 e = shflx(z[d], 16);
        z[d] = (p & 16) ? cmul(csub(z[d], e), W32p) : cadd(z[d], e);
    }
    #pragma unroll
    for (int d = 0; d < 8; d++) {
        float2 e = shflx(z[d], 8);
        z[d] = (p & 8) ? cmul(csub(e, z[d]), T2) : cadd(z[d], e);
    }
    #pragma unroll
    for (int d = 0; d < 8; d++) {
        float2 e = shflx(z[d], 4);
        z[d] = (p & 4) ? cmul(csub(e, z[d]), T3) : cadd(z[d], e);
    }
    #pragma unroll
    for (int d = 0; d < 8; d++) {
        float2 e = shflx(z[d], 2);
        float2 df = csub(e, z[d]);
        float2 tw = (p & 1) ? make_float2(df.y, -df.x) : df;
        z[d] = (p & 2) ? tw : cadd(z[d], e);
    }
    #pragma unroll
    for (int d = 0; d < 8; d++) {
        float2 e = shflx(z[d], 1);
        z[d] = (p & 1) ? csub(e, z[d]) : cadd(z[d], e);
    }

    // ---- publish all 512 bins: slot d holds X[8u + d], u = 2 br5(p) + hw ----
    const int u = 2 * (int)(__brev((unsigned)p) >> 27) + hw;
    BARF(grp);                             // level-1 reads complete before overwrite
    #pragma unroll
    for (int d = 0; d < 8; d++) sX[grp][9 * u + d] = z[d];   // PH(8u+d) = 9u+d
    BARF(grp);

    // ---- psycho tables for bins kb..kb+3 ----
    const int kb = 4 * t;
    const float4 cA4 = *(const float4*)&g_tabs.v[OFF_CA  + kb];
    const float4 cB4 = *(const float4*)&g_tabs.v[OFF_CB  + kb];
    const float4 dA4 = *(const float4*)&g_tabs.v[OFF_DA  + kb];
    const float4 dB4 = *(const float4*)&g_tabs.v[OFF_DB  + kb];
    const float4 at4 = *(const float4*)&g_tabs.v[OFF_ATH + kb];

    // ---- unpack bins kb..kb+3 (+ neighbors) from smem ----
    float pp[4], pt[4];
    #pragma unroll
    for (int i = 0; i < 4; i++) {
        int k = kb + i;
        float2 Xk = sX[grp][PH(k)];
        float2 Xc = sX[grp][PH((NFFT - k) & (NFFT - 1))];
        float spr = Xk.x + Xc.x, spi = Xk.y - Xc.y;
        float str = Xk.y + Xc.y, sti = Xc.x - Xk.x;
        pp[i] = 0.25f * (spr * spr + spi * spi) + 1e-12f;
        pt[i] = 0.25f * (str * str + sti * sti) + 1e-12f;
    }
    float ptm1 = 3.4e38f;
    if (t > 0) {
        int k = kb - 1;
        float2 Xk = sX[grp][PH(k)];
        float2 Xc = sX[grp][PH(NFFT - k)];
        float str = Xk.y + Xc.y, sti = Xc.x - Xk.x;
        ptm1 = 0.25f * (str * str + sti * sti) + 1e-12f;
    }
    float ptp4;
    {
        int k = kb + 4;                     // <= 256, conj formula valid incl. 256
        float2 Xk = sX[grp][PH(k)];
        float2 Xc = sX[grp][PH((NFFT - k) & (NFFT - 1))];
        float str = Xk.y + Xc.y, sti = Xc.x - Xk.x;
        ptp4 = 0.25f * (str * str + sti * sti) + 1e-12f;
    }

    // ---- tonal + scaled linear masker terms ----
    const float cAv[4] = { cA4.x, cA4.y, cA4.z, cA4.w };
    const float cBv[4] = { cB4.x, cB4.y, cB4.z, cB4.w };
    float av[4], bv[4];
    #pragma unroll
    for (int i = 0; i < 4; i++) {
        int k = kb + i;
        float pl = i ? pt[i - 1] : ptm1;
        float pr = (i < 3) ? pt[i + 1] : ptp4;
        bool tn = (k >= 1) && (pt[i] > pl) && (pt[i] > pr) && (pt[i] >= 1e-4f);
        av[i] = tn ? pt[i] * cAv[i] : 0.0f;
        bv[i] = tn ? pt[i] * cBv[i] : 0.0f;
    }
    float pa[4], sb[4];
    pa[0] = av[0];
    pa[1] = fmaxf(pa[0], av[1]);
    pa[2] = fmaxf(pa[1], av[2]);
    pa[3] = fmaxf(pa[2], av[3]);
    sb[3] = bv[3];
    sb[2] = fmaxf(sb[3], bv[2]);
    sb[1] = fmaxf(sb[2], bv[1]);
    sb[0] = fmaxf(sb[1], bv[0]);

    // ---- scan over 64 thread-aggregates (t order), 2-warp handoff ----
    float inc = pa[3];
    #pragma unroll
    for (int off = 1; off < 32; off <<= 1) {
        float o = __shfl_up_sync(FULLM, inc, off);
        if (lane >= off) inc = fmaxf(inc, o);
    }
    float exA = __shfl_up_sync(FULLM, inc, 1);
    if (lane == 0) exA = 0.0f;
    if (hw == 0 && lane == 31) sAg[grp] = inc;

    float rinc = sb[0];
    #pragma unroll
    for (int off = 1; off < 32; off <<= 1) {
        float o = __shfl_down_sync(FULLM, rinc, off);
        if (lane + off < 32) rinc = fmaxf(rinc, o);
    }
    float exB = __shfl_down_sync(FULLM, rinc, 1);
    if (lane == 31) exB = 0.0f;
    if (hw == 1 && lane == 0) sBg[grp] = rinc;
    BARF(grp);
    if (hw == 1) exA = fmaxf(exA, sAg[grp]);
    if (hw == 0) exB = fmaxf(exB, sBg[grp]);

    // ---- per-bin masking, weights, error ----
    const float dAv[4] = { dA4.x, dA4.y, dA4.z, dA4.w };
    const float dBv[4] = { dB4.x, dB4.y, dB4.z, dB4.w };
    const float atv[4] = { at4.x, at4.y, at4.z, at4.w };

    float contrib = 0.0f;
    #pragma unroll
    for (int i = 0; i < 4; i++) {
        float Ap = fmaxf(exA, pa[i]);
        float Bs = fmaxf(exB, sb[i]);
        float masking = fmaxf(Ap * dAv[i], Bs * dBv[i]);
        float combined = masking + atv[i];
        float w  = __log10f(pt[i] / (combined + 1e-12f) + 1.0f);
        float d  = sqrtf(pp[i]) - sqrtf(pt[i]);
        contrib += w * d * d;
    }
    if (t == 63) {                          // bin 256: never tonal, A-side only
        float2 X6 = sX[grp][PH(256)];
        float pp6 = X6.x * X6.x + 1e-12f;
        float pt6 = ptp4;                   // pt of bin 256 computed above
        float Ap = fmaxf(exA, pa[3]);       // prefix over all bins <= 255
        float combined = Ap * g_tabs.v[OFF_DA + 256] + g_tabs.v[OFF_ATH + 256];
        float w  = __log10f(pt6 / (combined + 1e-12f) + 1.0f);
        float d  = sqrtf(pp6) - sqrtf(pt6);
        contrib += w * d * d;
    }

    // ---- block reduction (8 warps) ----
    float v = contrib;
    #pragma unroll
    for (int off = 16; off > 0; off >>= 1)
        v += __shfl_down_sync(FULLM, v, off);
    if (lane == 0) redw[wrp] = v;
    __syncthreads();
    const int bid = blockIdx.y * (NT / NFR) + blockIdx.x;
    if (tid == 0) {
        float s = redw[0];
        #pragma unroll
        for (int q = 1; q < 8; q++) s += redw[q];
        g_partial[bid] = s;
    }

    // ---- last block: deterministic global reduction ----
    __threadfence();
    if (tid == 0) {
        unsigned r = atomicAdd(&g_count, 1u);
        s_last = (r == NBLKS - 1) ? 1 : 0;
    }
    __syncthreads();
    if (s_last) {
        float s = 0.0f;
        for (int i = tid; i < NBLKS; i += NTHREADS) s += g_partial[i];
        #pragma unroll
        for (int off = 16; off > 0; off >>= 1)
            s += __shfl_down_sync(FULLM, s, off);
        if (lane == 0) redw[wrp] = s;
        __syncthreads();
        if (tid == 0) {
            float s2 = redw[0];
            #pragma unroll
            for (int q = 1; q < 8; q++) s2 += redw[q];
            out[0] = s2 * (1.0f / (float)(BATCH * NBINS * NT));
            g_count = 0;
        }
    }
}

extern "C" void kernel_launch(void* const* d_in, const int* in_sizes, int n_in,
                              void* d_out, int out_size) {
    const float* pred = (const float*)d_in[0];
    const float* tgt  = (const float*)d_in[1];
    float* out = (float*)d_out;
    dim3 grid(NT / NFR, BATCH);
    pam_kernel<<<grid, NTHREADS>>>(pred, tgt, out);
}